// round 1
// baseline (speedup 1.0000x reference)
#include <cuda_runtime.h>

#define B_   2
#define S_   2048
#define DM_  2048
#define H_   32
#define KV_  8
#define HD_  64
#define GRP_ (H_ / KV_)   // 4

// ---------------- scratch (device globals; no allocation allowed) -------------
__device__ float g_q[(size_t)B_ * S_ * H_ * HD_];    // 32 MB
__device__ float g_k[(size_t)B_ * S_ * KV_ * HD_];   //  8 MB
__device__ float g_v[(size_t)B_ * S_ * KV_ * HD_];   //  8 MB
__device__ float g_ao[(size_t)B_ * S_ * H_ * HD_];   // 32 MB

// ---------------- SGEMM: C[M,N] = A[M,K] @ B[K,N] (+ bias[N]) -----------------
// 128x128 tile, k-tile 8, 256 threads, 8x8 per-thread microtile.
// Dims must be multiples of the tile sizes (they are for this problem).
__global__ __launch_bounds__(256) void sgemm_bias(
    const float* __restrict__ A, const float* __restrict__ B,
    const float* __restrict__ bias, float* __restrict__ C,
    int M, int N, int K)
{
    __shared__ float As[8][128];
    __shared__ float Bs[8][128];

    const int tid = threadIdx.x;
    const int bm = blockIdx.y * 128;
    const int bn = blockIdx.x * 128;

    const int tm = (tid >> 4) << 3;   // 0..120 step 8
    const int tn = (tid & 15) << 3;   // 0..120 step 8

    // A-tile load mapping: 128 rows x 8 k, one float4 per thread
    const int am = tid >> 1;            // 0..127
    const int ak = (tid & 1) << 2;      // 0 or 4
    // B-tile load mapping: 8 rows x 128 cols, one float4 per thread
    const int bk  = tid >> 5;           // 0..7
    const int bn4 = (tid & 31) << 2;    // 0..124

    const float* Aptr = A + (size_t)(bm + am) * K + ak;
    const float* Bptr = B + (size_t)bk * N + bn + bn4;

    float acc[8][8];
#pragma unroll
    for (int i = 0; i < 8; i++)
#pragma unroll
        for (int j = 0; j < 8; j++) acc[i][j] = 0.0f;

    for (int k0 = 0; k0 < K; k0 += 8) {
        const float4 av = *(const float4*)(Aptr + k0);
        const float4 bv = *(const float4*)(Bptr + (size_t)k0 * N);

        __syncthreads();   // previous tile fully consumed
        As[ak + 0][am] = av.x;
        As[ak + 1][am] = av.y;
        As[ak + 2][am] = av.z;
        As[ak + 3][am] = av.w;
        *(float4*)&Bs[bk][bn4] = bv;
        __syncthreads();

#pragma unroll
        for (int kk = 0; kk < 8; kk++) {
            float a[8], b[8];
            *(float4*)(a)     = *(const float4*)&As[kk][tm];
            *(float4*)(a + 4) = *(const float4*)&As[kk][tm + 4];
            *(float4*)(b)     = *(const float4*)&Bs[kk][tn];
            *(float4*)(b + 4) = *(const float4*)&Bs[kk][tn + 4];
#pragma unroll
            for (int i = 0; i < 8; i++)
#pragma unroll
                for (int j = 0; j < 8; j++) acc[i][j] += a[i] * b[j];
        }
    }

    float breg[8];
#pragma unroll
    for (int j = 0; j < 8; j++) breg[j] = bias ? bias[bn + tn + j] : 0.0f;

#pragma unroll
    for (int i = 0; i < 8; i++) {
        float* cp = C + (size_t)(bm + tm + i) * N + bn + tn;
        float4 o0, o1;
        o0.x = acc[i][0] + breg[0];  o0.y = acc[i][1] + breg[1];
        o0.z = acc[i][2] + breg[2];  o0.w = acc[i][3] + breg[3];
        o1.x = acc[i][4] + breg[4];  o1.y = acc[i][5] + breg[5];
        o1.z = acc[i][6] + breg[6];  o1.w = acc[i][7] + breg[7];
        *(float4*)(cp)     = o0;
        *(float4*)(cp + 4) = o1;
    }
}

// ---------------- RoPE (in place) ---------------------------------------------
// x layout: [row = b*S + s][h*HD + d], cos/sin: [row][d] (B,S,HD contiguous)
__global__ void rope_kernel(float* __restrict__ x,
                            const float* __restrict__ cosb,
                            const float* __restrict__ sinb,
                            int rows, int nh)
{
    int idx = blockIdx.x * blockDim.x + threadIdx.x;
    int total = rows * nh * (HD_ / 2);
    if (idx >= total) return;
    int d = idx & 31;
    int h = (idx >> 5) % nh;
    int r = idx / (32 * nh);

    float* p = x + (size_t)r * nh * HD_ + h * HD_;
    const float* cp = cosb + (size_t)r * HD_;
    const float* sp = sinb + (size_t)r * HD_;

    float x1 = p[d], x2 = p[d + 32];
    float c1 = cp[d], s1 = sp[d];
    float c2 = cp[d + 32], s2 = sp[d + 32];
    p[d]      = x1 * c1 - x2 * s1;
    p[d + 32] = x2 * c2 + x1 * s2;
}

// ---------------- Flash-style causal GQA attention (fp32) ---------------------
// grid: (S/128, H, B); 128 threads; thread t owns q row m0+t.
// K/V staged in smem 32 rows at a time (broadcast LDS), scores staged in
// padded smem row per thread, online softmax, acc[64] in registers.
#define AM 128
#define AN 32

__global__ __launch_bounds__(128) void attn_kernel(
    const float* __restrict__ q, const float* __restrict__ k,
    const float* __restrict__ v, const int* __restrict__ amask,
    float* __restrict__ o)
{
    __shared__ float Ksh[AN][HD_];
    __shared__ float Vsh[AN][HD_];
    __shared__ float ssh[AM][AN + 1];
    __shared__ int   msh[AN];

    const int t  = threadIdx.x;
    const int m0 = blockIdx.x * AM;
    const int h  = blockIdx.y;
    const int b  = blockIdx.z;
    const int row = m0 + t;
    const int kvh = h / GRP_;

    // load q row into registers (contiguous 64 floats per thread)
    float qr[HD_];
    {
        const float4* qp = (const float4*)(q + ((size_t)(b * S_ + row) * H_ + h) * HD_);
#pragma unroll
        for (int i = 0; i < 16; i++) {
            float4 f = qp[i];
            qr[4 * i + 0] = f.x; qr[4 * i + 1] = f.y;
            qr[4 * i + 2] = f.z; qr[4 * i + 3] = f.w;
        }
    }

    float acc[HD_];
#pragma unroll
    for (int d = 0; d < HD_; d++) acc[d] = 0.0f;
    float mrun = -INFINITY;
    float lrun = 0.0f;

    const int ntiles = (m0 + AM) / AN;
    for (int tile = 0; tile < ntiles; tile++) {
        const int j0 = tile * AN;

        __syncthreads();  // previous tile fully consumed
        // load K/V tile: 32 rows x 16 float4 = 512 float4, 4 per thread
#pragma unroll
        for (int i = 0; i < 4; i++) {
            int idx = i * 128 + t;
            int j  = idx >> 4;
            int dq = idx & 15;
            size_t base = ((size_t)(b * S_ + j0 + j) * KV_ + kvh) * HD_;
            ((float4*)&Ksh[j][0])[dq] = *(const float4*)(k + base + dq * 4);
            ((float4*)&Vsh[j][0])[dq] = *(const float4*)(v + base + dq * 4);
        }
        if (t < AN) msh[t] = amask[b * S_ + j0 + t];
        __syncthreads();

        // scores for this thread's row
        float smax = -INFINITY;
        for (int j = 0; j < AN; j++) {
            float d0 = 0.f, d1 = 0.f, d2 = 0.f, d3 = 0.f;
#pragma unroll
            for (int dq = 0; dq < 16; dq += 4) {
                float4 k0v = *(const float4*)&Ksh[j][(dq + 0) * 4];
                float4 k1v = *(const float4*)&Ksh[j][(dq + 1) * 4];
                float4 k2v = *(const float4*)&Ksh[j][(dq + 2) * 4];
                float4 k3v = *(const float4*)&Ksh[j][(dq + 3) * 4];
                d0 += qr[dq*4+0]*k0v.x + qr[dq*4+1]*k0v.y + qr[dq*4+2]*k0v.z + qr[dq*4+3]*k0v.w;
                d1 += qr[dq*4+4]*k1v.x + qr[dq*4+5]*k1v.y + qr[dq*4+6]*k1v.z + qr[dq*4+7]*k1v.w;
                d2 += qr[dq*4+8]*k2v.x + qr[dq*4+9]*k2v.y + qr[dq*4+10]*k2v.z + qr[dq*4+11]*k2v.w;
                d3 += qr[dq*4+12]*k3v.x + qr[dq*4+13]*k3v.y + qr[dq*4+14]*k3v.z + qr[dq*4+15]*k3v.w;
            }
            float sv = (d0 + d1 + d2 + d3) * 0.125f;   // 1/sqrt(64)
            bool valid = ((j0 + j) <= row) && (msh[j] != 0);
            sv = valid ? sv : -INFINITY;
            ssh[t][j] = sv;
            smax = fmaxf(smax, sv);
        }

        float mnew = fmaxf(mrun, smax);
        if (mnew > -INFINITY) {
            float corr = __expf(mrun - mnew);   // 0 when mrun == -inf
            float lsum = 0.f;
            for (int j = 0; j < AN; j++) {
                float p = __expf(ssh[t][j] - mnew);
                ssh[t][j] = p;
                lsum += p;
            }
            lrun = lrun * corr + lsum;
#pragma unroll
            for (int d = 0; d < HD_; d++) acc[d] *= corr;
            for (int j = 0; j < AN; j++) {
                float p = ssh[t][j];
#pragma unroll
                for (int dq = 0; dq < 16; dq++) {
                    float4 vv = *(const float4*)&Vsh[j][dq * 4];
                    acc[dq*4+0] += p * vv.x;
                    acc[dq*4+1] += p * vv.y;
                    acc[dq*4+2] += p * vv.z;
                    acc[dq*4+3] += p * vv.w;
                }
            }
            mrun = mnew;
        }
    }

    float inv = 1.0f / lrun;
    float4* op = (float4*)(o + ((size_t)(b * S_ + row) * H_ + h) * HD_);
#pragma unroll
    for (int i = 0; i < 16; i++) {
        float4 f;
        f.x = acc[4*i+0] * inv; f.y = acc[4*i+1] * inv;
        f.z = acc[4*i+2] * inv; f.w = acc[4*i+3] * inv;
        op[i] = f;
    }
}

// ---------------- launch ------------------------------------------------------
extern "C" void kernel_launch(void* const* d_in, const int* in_sizes, int n_in,
                              void* d_out, int out_size)
{
    const float* hs    = (const float*)d_in[0];
    const int*   amask = (const int*)  d_in[1];
    const float* cosb  = (const float*)d_in[2];
    const float* sinb  = (const float*)d_in[3];
    const float* W_q   = (const float*)d_in[4];
    const float* W_k   = (const float*)d_in[5];
    const float* W_v   = (const float*)d_in[6];
    const float* b_v   = (const float*)d_in[7];
    const float* W_o   = (const float*)d_in[8];
    const float* b_o   = (const float*)d_in[9];
    float* out = (float*)d_out;

    float *qb, *kb, *vb, *aob;
    cudaGetSymbolAddress((void**)&qb,  g_q);
    cudaGetSymbolAddress((void**)&kb,  g_k);
    cudaGetSymbolAddress((void**)&vb,  g_v);
    cudaGetSymbolAddress((void**)&aob, g_ao);

    const int M = B_ * S_;          // 4096
    const int NQ = H_ * HD_;        // 2048
    const int NKV = KV_ * HD_;      // 512

    // QKV projections
    sgemm_bias<<<dim3(NQ / 128,  M / 128), 256>>>(hs, W_q, nullptr, qb, M, NQ,  DM_);
    sgemm_bias<<<dim3(NKV / 128, M / 128), 256>>>(hs, W_k, nullptr, kb, M, NKV, DM_);
    sgemm_bias<<<dim3(NKV / 128, M / 128), 256>>>(hs, W_v, b_v,     vb, M, NKV, DM_);

    // RoPE
    {
        int tq = M * H_ * (HD_ / 2);
        rope_kernel<<<(tq + 255) / 256, 256>>>(qb, cosb, sinb, M, H_);
        int tk = M * KV_ * (HD_ / 2);
        rope_kernel<<<(tk + 255) / 256, 256>>>(kb, cosb, sinb, M, KV_);
    }

    // Attention
    attn_kernel<<<dim3(S_ / AM, H_, B_), AM>>>(qb, kb, vb, amask, aob);

    // Output projection
    sgemm_bias<<<dim3(NQ / 128, M / 128), 256>>>(aob, W_o, b_o, out, M, NQ, DM_);
}

// round 3
// speedup vs baseline: 1.4667x; 1.4667x over previous
#include <cuda_runtime.h>
#include <cuda_bf16.h>
#include <cstdint>

#define B_   2
#define S_   2048
#define DM_  2048
#define H_   32
#define KV_  8
#define HD_  64
#define GRP_ (H_ / KV_)   // 4

// ============================ PTX helpers (base sm_103 safe) ==================
__device__ __forceinline__ uint32_t smem_u32(const void* p) {
    uint32_t a;
    asm("{ .reg .u64 t; cvta.to.shared.u64 t, %1; cvt.u32.u64 %0, t; }"
        : "=r"(a) : "l"(p));
    return a;
}
__device__ __forceinline__ void cp_async16(uint32_t s, const void* g) {
    asm volatile("cp.async.cg.shared.global [%0], [%1], 16;" :: "r"(s), "l"(g));
}
#define CP_COMMIT() asm volatile("cp.async.commit_group;" ::: "memory")
#define CP_WAIT(n)  asm volatile("cp.async.wait_group %0;" :: "n"(n) : "memory")

__device__ __forceinline__ void ldsm_x4(uint32_t addr, uint32_t& r0, uint32_t& r1,
                                        uint32_t& r2, uint32_t& r3) {
    asm volatile("ldmatrix.sync.aligned.m8n8.x4.shared.b16 {%0,%1,%2,%3}, [%4];"
                 : "=r"(r0), "=r"(r1), "=r"(r2), "=r"(r3) : "r"(addr));
}
__device__ __forceinline__ void mma_bf16(float* d, const uint32_t* a,
                                         uint32_t b0, uint32_t b1) {
    asm volatile("mma.sync.aligned.m16n8k16.row.col.f32.bf16.bf16.f32 "
                 "{%0,%1,%2,%3}, {%4,%5,%6,%7}, {%8,%9}, {%0,%1,%2,%3};"
                 : "+f"(d[0]), "+f"(d[1]), "+f"(d[2]), "+f"(d[3])
                 : "r"(a[0]), "r"(a[1]), "r"(a[2]), "r"(a[3]), "r"(b0), "r"(b1));
}

// ============================ scratch =========================================
__device__ float g_q [(size_t)B_ * S_ * H_ * HD_];     // 32 MB
__device__ float g_k [(size_t)B_ * S_ * KV_ * HD_];    //  8 MB
__device__ float g_v [(size_t)B_ * S_ * KV_ * HD_];    //  8 MB
__device__ float g_ao[(size_t)B_ * S_ * H_ * HD_];     // 32 MB

__device__ __nv_bfloat16 g_hsh[(size_t)B_ * S_ * DM_];   // 16 MB
__device__ __nv_bfloat16 g_hsl[(size_t)B_ * S_ * DM_];
__device__ __nv_bfloat16 g_aoh[(size_t)B_ * S_ * DM_];
__device__ __nv_bfloat16 g_aol[(size_t)B_ * S_ * DM_];
__device__ __nv_bfloat16 g_wqh[(size_t)DM_ * H_ * HD_];  // [N,K] transposed
__device__ __nv_bfloat16 g_wql[(size_t)DM_ * H_ * HD_];
__device__ __nv_bfloat16 g_wkh[(size_t)DM_ * KV_ * HD_];
__device__ __nv_bfloat16 g_wkl[(size_t)DM_ * KV_ * HD_];
__device__ __nv_bfloat16 g_wvh[(size_t)DM_ * KV_ * HD_];
__device__ __nv_bfloat16 g_wvl[(size_t)DM_ * KV_ * HD_];
__device__ __nv_bfloat16 g_woh[(size_t)DM_ * H_ * HD_];
__device__ __nv_bfloat16 g_wol[(size_t)DM_ * H_ * HD_];

// ==================== fp32 -> bf16 hi/lo split (row-major) ====================
__global__ void split_kernel(const float* __restrict__ x,
                             __nv_bfloat16* __restrict__ h,
                             __nv_bfloat16* __restrict__ l, int n4)
{
    int i = blockIdx.x * blockDim.x + threadIdx.x;
    if (i >= n4) return;
    float4 v = ((const float4*)x)[i];
    __nv_bfloat16 h0 = __float2bfloat16(v.x);
    __nv_bfloat16 h1 = __float2bfloat16(v.y);
    __nv_bfloat16 h2 = __float2bfloat16(v.z);
    __nv_bfloat16 h3 = __float2bfloat16(v.w);
    __nv_bfloat16 l0 = __float2bfloat16(v.x - __bfloat162float(h0));
    __nv_bfloat16 l1 = __float2bfloat16(v.y - __bfloat162float(h1));
    __nv_bfloat16 l2 = __float2bfloat16(v.z - __bfloat162float(h2));
    __nv_bfloat16 l3 = __float2bfloat16(v.w - __bfloat162float(h3));
    ((__nv_bfloat162*)h)[2 * i]     = __nv_bfloat162(h0, h1);
    ((__nv_bfloat162*)h)[2 * i + 1] = __nv_bfloat162(h2, h3);
    ((__nv_bfloat162*)l)[2 * i]     = __nv_bfloat162(l0, l1);
    ((__nv_bfloat162*)l)[2 * i + 1] = __nv_bfloat162(l2, l3);
}

// ============ fp32 [K,N] -> bf16 hi/lo transposed [N,K] =======================
__global__ void splitT_kernel(const float* __restrict__ W,
                              __nv_bfloat16* __restrict__ h,
                              __nv_bfloat16* __restrict__ l, int K, int N)
{
    __shared__ float ts[32][33];
    int n0 = blockIdx.x * 32, k0 = blockIdx.y * 32;
    int tx = threadIdx.x, ty = threadIdx.y;
    for (int i = ty; i < 32; i += 8)
        ts[i][tx] = W[(size_t)(k0 + i) * N + n0 + tx];
    __syncthreads();
    for (int i = ty; i < 32; i += 8) {
        float x = ts[tx][i];     // element (k = k0+tx, n = n0+i)
        __nv_bfloat16 hv = __float2bfloat16(x);
        __nv_bfloat16 lv = __float2bfloat16(x - __bfloat162float(hv));
        size_t o = (size_t)(n0 + i) * K + k0 + tx;
        h[o] = hv;
        l[o] = lv;
    }
}

// =================== warp-MMA split-bf16 GEMM (HMMA path) =====================
// C[M,N] = A[M,K] @ B[K,N] (+bias); A as Ah/Al bf16 [M,K]; B pre-transposed
// as Bh/Bl bf16 [N,K]. CTA tile 128x128, 8 warps (2x4), warp tile 64x32,
// K-tile 32, 2-stage cp.async pipeline. 3-term compensated accumulation.
#define ROWB    80                  // padded smem row bytes (32 bf16 + 8 pad)
#define TILE_B  (128 * ROWB)        // 10240
#define STAGE_B (4 * TILE_B)        // 40960 : Ah | Al | Bh | Bl
#define GSMEM   (2 * STAGE_B)       // 81920

__global__ __launch_bounds__(256) void gemm_mma(
    const __nv_bfloat16* __restrict__ Ah, const __nv_bfloat16* __restrict__ Al,
    const __nv_bfloat16* __restrict__ Bh, const __nv_bfloat16* __restrict__ Bl,
    const float* __restrict__ bias, float* __restrict__ C,
    int M, int N, int K)
{
    extern __shared__ char smem[];
    const uint32_t sb = smem_u32(smem);
    const int tid  = threadIdx.x;
    const int lane = tid & 31;
    const int wid  = tid >> 5;
    const int wm   = wid >> 2;      // 0..1
    const int wn   = wid & 3;       // 0..3
    const int m0 = blockIdx.y * 128;
    const int n0 = blockIdx.x * 128;

    float acc[4][4][4];
#pragma unroll
    for (int i = 0; i < 4; i++)
#pragma unroll
        for (int j = 0; j < 4; j++)
#pragma unroll
            for (int r = 0; r < 4; r++) acc[i][j][r] = 0.0f;

    const int nt = K / 32;

    // ---- stage loader: 2 x 16B chunks per thread per tile --------------------
    const int r0c = tid >> 2, c0c = tid & 3;            // chunk 0: cid = tid
    const int r1c = (tid + 256) >> 2, c1c = tid & 3;    // chunk 1: cid = tid+256

#define LOAD_STAGE(kt)                                                          \
    do {                                                                        \
        const int _k0 = (kt) * 32;                                              \
        const uint32_t _st = sb + ((kt) & 1) * STAGE_B;                         \
        size_t _ga0 = (size_t)(m0 + r0c) * K + _k0 + c0c * 8;                   \
        size_t _gb0 = (size_t)(n0 + r0c) * K + _k0 + c0c * 8;                   \
        size_t _ga1 = (size_t)(m0 + r1c) * K + _k0 + c1c * 8;                   \
        size_t _gb1 = (size_t)(n0 + r1c) * K + _k0 + c1c * 8;                   \
        uint32_t _s0 = _st + r0c * ROWB + c0c * 16;                             \
        uint32_t _s1 = _st + r1c * ROWB + c1c * 16;                             \
        cp_async16(_s0,              Ah + _ga0);                                \
        cp_async16(_s0 + TILE_B,     Al + _ga0);                                \
        cp_async16(_s0 + 2 * TILE_B, Bh + _gb0);                                \
        cp_async16(_s0 + 3 * TILE_B, Bl + _gb0);                                \
        cp_async16(_s1,              Ah + _ga1);                                \
        cp_async16(_s1 + TILE_B,     Al + _ga1);                                \
        cp_async16(_s1 + 2 * TILE_B, Bh + _gb1);                                \
        cp_async16(_s1 + 3 * TILE_B, Bl + _gb1);                                \
    } while (0)

    LOAD_STAGE(0);
    CP_COMMIT();

    const uint32_t a_lane_off = (uint32_t)(wm * 64 + (lane & 15)) * ROWB + ((lane >> 4) << 4);
    const uint32_t b_lane_off = (uint32_t)(wn * 32 + (lane & 15)) * ROWB + ((lane >> 4) << 4);

    for (int kt = 0; kt < nt; kt++) {
        if (kt + 1 < nt) { LOAD_STAGE(kt + 1); CP_COMMIT(); CP_WAIT(1); }
        else             { CP_WAIT(0); }
        __syncthreads();

        const uint32_t st = sb + (kt & 1) * STAGE_B;
#pragma unroll
        for (int ks = 0; ks < 2; ks++) {
            const uint32_t kof = ks * 32;

            // B fragments: bh[j*2+{0,1}] for n-tiles j=0..3 (two x4 loads each of hi/lo)
            uint32_t bh[8], bl[8];
#pragma unroll
            for (int p = 0; p < 2; p++) {
                uint32_t baddr = st + 2 * TILE_B + b_lane_off + (uint32_t)(p * 16) * ROWB + kof;
                uint32_t q0, q1, q2, q3;
                ldsm_x4(baddr, q0, q1, q2, q3);
                bh[(2 * p) * 2 + 0] = q0; bh[(2 * p + 1) * 2 + 0] = q1;
                bh[(2 * p) * 2 + 1] = q2; bh[(2 * p + 1) * 2 + 1] = q3;
                ldsm_x4(baddr + TILE_B, q0, q1, q2, q3);
                bl[(2 * p) * 2 + 0] = q0; bl[(2 * p + 1) * 2 + 0] = q1;
                bl[(2 * p) * 2 + 1] = q2; bl[(2 * p + 1) * 2 + 1] = q3;
            }

            // A hi fragments
            uint32_t a[4][4];
#pragma unroll
            for (int i = 0; i < 4; i++)
                ldsm_x4(st + a_lane_off + (uint32_t)(i * 16) * ROWB + kof,
                        a[i][0], a[i][1], a[i][2], a[i][3]);

            // Ah*Bh
#pragma unroll
            for (int i = 0; i < 4; i++)
#pragma unroll
                for (int j = 0; j < 4; j++)
                    mma_bf16(acc[i][j], a[i], bh[2 * j], bh[2 * j + 1]);
            // Ah*Bl
#pragma unroll
            for (int i = 0; i < 4; i++)
#pragma unroll
                for (int j = 0; j < 4; j++)
                    mma_bf16(acc[i][j], a[i], bl[2 * j], bl[2 * j + 1]);

            // A lo fragments (reuse regs)
#pragma unroll
            for (int i = 0; i < 4; i++)
                ldsm_x4(st + TILE_B + a_lane_off + (uint32_t)(i * 16) * ROWB + kof,
                        a[i][0], a[i][1], a[i][2], a[i][3]);
            // Al*Bh
#pragma unroll
            for (int i = 0; i < 4; i++)
#pragma unroll
                for (int j = 0; j < 4; j++)
                    mma_bf16(acc[i][j], a[i], bh[2 * j], bh[2 * j + 1]);
        }
        __syncthreads();
    }
#undef LOAD_STAGE

    // ---- epilogue ------------------------------------------------------------
#pragma unroll
    for (int i = 0; i < 4; i++) {
        const int row = m0 + wm * 64 + i * 16 + (lane >> 2);
#pragma unroll
        for (int j = 0; j < 4; j++) {
            const int col = n0 + wn * 32 + j * 8 + (lane & 3) * 2;
            float b0 = 0.f, b1 = 0.f;
            if (bias) { b0 = bias[col]; b1 = bias[col + 1]; }
            float2 v0, v1;
            v0.x = acc[i][j][0] + b0; v0.y = acc[i][j][1] + b1;
            v1.x = acc[i][j][2] + b0; v1.y = acc[i][j][3] + b1;
            *(float2*)(C + (size_t)row * N + col)       = v0;
            *(float2*)(C + (size_t)(row + 8) * N + col) = v1;
        }
    }
}

// ================================ RoPE ========================================
__global__ void rope_kernel(float* __restrict__ x,
                            const float* __restrict__ cosb,
                            const float* __restrict__ sinb,
                            int rows, int nh)
{
    int idx = blockIdx.x * blockDim.x + threadIdx.x;
    int total = rows * nh * (HD_ / 2);
    if (idx >= total) return;
    int d = idx & 31;
    int h = (idx >> 5) % nh;
    int r = idx / (32 * nh);

    float* p = x + (size_t)r * nh * HD_ + h * HD_;
    const float* cp = cosb + (size_t)r * HD_;
    const float* sp = sinb + (size_t)r * HD_;

    float x1 = p[d], x2 = p[d + 32];
    p[d]      = x1 * cp[d]      - x2 * sp[d];
    p[d + 32] = x2 * cp[d + 32] + x1 * sp[d + 32];
}

// ================= flash-style causal GQA attention (fp32) ====================
#define AM 128
#define AN 32

__global__ __launch_bounds__(128) void attn_kernel(
    const float* __restrict__ q, const float* __restrict__ k,
    const float* __restrict__ v, const int* __restrict__ amask,
    float* __restrict__ o)
{
    __shared__ float Ksh[AN][HD_];
    __shared__ float Vsh[AN][HD_];
    __shared__ float ssh[AM][AN + 1];
    __shared__ int   msh[AN];

    const int t  = threadIdx.x;
    const int m0 = blockIdx.x * AM;
    const int h  = blockIdx.y;
    const int b  = blockIdx.z;
    const int row = m0 + t;
    const int kvh = h / GRP_;

    float qr[HD_];
    {
        const float4* qp = (const float4*)(q + ((size_t)(b * S_ + row) * H_ + h) * HD_);
#pragma unroll
        for (int i = 0; i < 16; i++) {
            float4 f = qp[i];
            qr[4 * i + 0] = f.x; qr[4 * i + 1] = f.y;
            qr[4 * i + 2] = f.z; qr[4 * i + 3] = f.w;
        }
    }

    float acc[HD_];
#pragma unroll
    for (int d = 0; d < HD_; d++) acc[d] = 0.0f;
    float mrun = -INFINITY;
    float lrun = 0.0f;

    const int ntiles = (m0 + AM) / AN;
    for (int tile = 0; tile < ntiles; tile++) {
        const int j0 = tile * AN;

        __syncthreads();
#pragma unroll
        for (int i = 0; i < 4; i++) {
            int idx = i * 128 + t;
            int j  = idx >> 4;
            int dq = idx & 15;
            size_t base = ((size_t)(b * S_ + j0 + j) * KV_ + kvh) * HD_;
            ((float4*)&Ksh[j][0])[dq] = *(const float4*)(k + base + dq * 4);
            ((float4*)&Vsh[j][0])[dq] = *(const float4*)(v + base + dq * 4);
        }
        if (t < AN) msh[t] = amask[b * S_ + j0 + t];
        __syncthreads();

        float smax = -INFINITY;
        for (int j = 0; j < AN; j++) {
            float d0 = 0.f, d1 = 0.f, d2 = 0.f, d3 = 0.f;
#pragma unroll
            for (int dq = 0; dq < 16; dq += 4) {
                float4 k0v = *(const float4*)&Ksh[j][(dq + 0) * 4];
                float4 k1v = *(const float4*)&Ksh[j][(dq + 1) * 4];
                float4 k2v = *(const float4*)&Ksh[j][(dq + 2) * 4];
                float4 k3v = *(const float4*)&Ksh[j][(dq + 3) * 4];
                d0 += qr[dq*4+0]*k0v.x + qr[dq*4+1]*k0v.y + qr[dq*4+2]*k0v.z + qr[dq*4+3]*k0v.w;
                d1 += qr[dq*4+4]*k1v.x + qr[dq*4+5]*k1v.y + qr[dq*4+6]*k1v.z + qr[dq*4+7]*k1v.w;
                d2 += qr[dq*4+8]*k2v.x + qr[dq*4+9]*k2v.y + qr[dq*4+10]*k2v.z + qr[dq*4+11]*k2v.w;
                d3 += qr[dq*4+12]*k3v.x + qr[dq*4+13]*k3v.y + qr[dq*4+14]*k3v.z + qr[dq*4+15]*k3v.w;
            }
            float sv = (d0 + d1 + d2 + d3) * 0.125f;
            bool valid = ((j0 + j) <= row) && (msh[j] != 0);
            sv = valid ? sv : -INFINITY;
            ssh[t][j] = sv;
            smax = fmaxf(smax, sv);
        }

        float mnew = fmaxf(mrun, smax);
        if (mnew > -INFINITY) {
            float corr = __expf(mrun - mnew);
            float lsum = 0.f;
            for (int j = 0; j < AN; j++) {
                float p = __expf(ssh[t][j] - mnew);
                ssh[t][j] = p;
                lsum += p;
            }
            lrun = lrun * corr + lsum;
#pragma unroll
            for (int d = 0; d < HD_; d++) acc[d] *= corr;
            for (int j = 0; j < AN; j++) {
                float p = ssh[t][j];
#pragma unroll
                for (int dq = 0; dq < 16; dq++) {
                    float4 vv = *(const float4*)&Vsh[j][dq * 4];
                    acc[dq*4+0] += p * vv.x;
                    acc[dq*4+1] += p * vv.y;
                    acc[dq*4+2] += p * vv.z;
                    acc[dq*4+3] += p * vv.w;
                }
            }
            mrun = mnew;
        }
    }

    float inv = 1.0f / lrun;
    float4* op = (float4*)(o + ((size_t)(b * S_ + row) * H_ + h) * HD_);
#pragma unroll
    for (int i = 0; i < 16; i++) {
        float4 f;
        f.x = acc[4*i+0] * inv; f.y = acc[4*i+1] * inv;
        f.z = acc[4*i+2] * inv; f.w = acc[4*i+3] * inv;
        op[i] = f;
    }
}

// ================================ launch ======================================
extern "C" void kernel_launch(void* const* d_in, const int* in_sizes, int n_in,
                              void* d_out, int out_size)
{
    const float* hs    = (const float*)d_in[0];
    const int*   amask = (const int*)  d_in[1];
    const float* cosb  = (const float*)d_in[2];
    const float* sinb  = (const float*)d_in[3];
    const float* W_q   = (const float*)d_in[4];
    const float* W_k   = (const float*)d_in[5];
    const float* W_v   = (const float*)d_in[6];
    const float* b_v   = (const float*)d_in[7];
    const float* W_o   = (const float*)d_in[8];
    const float* b_o   = (const float*)d_in[9];
    float* out = (float*)d_out;

    float *qb, *kb, *vb, *aob;
    cudaGetSymbolAddress((void**)&qb,  g_q);
    cudaGetSymbolAddress((void**)&kb,  g_k);
    cudaGetSymbolAddress((void**)&vb,  g_v);
    cudaGetSymbolAddress((void**)&aob, g_ao);
    __nv_bfloat16 *hsh, *hsl, *aoh, *aol, *wqh, *wql, *wkh, *wkl, *wvh, *wvl, *woh, *wol;
    cudaGetSymbolAddress((void**)&hsh, g_hsh);
    cudaGetSymbolAddress((void**)&hsl, g_hsl);
    cudaGetSymbolAddress((void**)&aoh, g_aoh);
    cudaGetSymbolAddress((void**)&aol, g_aol);
    cudaGetSymbolAddress((void**)&wqh, g_wqh);
    cudaGetSymbolAddress((void**)&wql, g_wql);
    cudaGetSymbolAddress((void**)&wkh, g_wkh);
    cudaGetSymbolAddress((void**)&wkl, g_wkl);
    cudaGetSymbolAddress((void**)&wvh, g_wvh);
    cudaGetSymbolAddress((void**)&wvl, g_wvl);
    cudaGetSymbolAddress((void**)&woh, g_woh);
    cudaGetSymbolAddress((void**)&wol, g_wol);

    cudaFuncSetAttribute(gemm_mma,
                         cudaFuncAttributeMaxDynamicSharedMemorySize, GSMEM);

    const int M   = B_ * S_;     // 4096
    const int NQ  = H_ * HD_;    // 2048
    const int NKV = KV_ * HD_;   // 512

    // input conversions
    split_kernel<<<(M * DM_ / 4 + 255) / 256, 256>>>(hs, hsh, hsl, M * DM_ / 4);
    splitT_kernel<<<dim3(NQ / 32,  DM_ / 32), dim3(32, 8)>>>(W_q, wqh, wql, DM_, NQ);
    splitT_kernel<<<dim3(NKV / 32, DM_ / 32), dim3(32, 8)>>>(W_k, wkh, wkl, DM_, NKV);
    splitT_kernel<<<dim3(NKV / 32, DM_ / 32), dim3(32, 8)>>>(W_v, wvh, wvl, DM_, NKV);
    splitT_kernel<<<dim3(DM_ / 32, NQ  / 32), dim3(32, 8)>>>(W_o, woh, wol, NQ, DM_);

    // QKV projections (tensor cores)
    gemm_mma<<<dim3(NQ / 128,  M / 128), 256, GSMEM>>>(hsh, hsl, wqh, wql, nullptr, qb, M, NQ,  DM_);
    gemm_mma<<<dim3(NKV / 128, M / 128), 256, GSMEM>>>(hsh, hsl, wkh, wkl, nullptr, kb, M, NKV, DM_);
    gemm_mma<<<dim3(NKV / 128, M / 128), 256, GSMEM>>>(hsh, hsl, wvh, wvl, b_v,    vb, M, NKV, DM_);

    // RoPE
    rope_kernel<<<(M * H_  * (HD_ / 2) + 255) / 256, 256>>>(qb, cosb, sinb, M, H_);
    rope_kernel<<<(M * KV_ * (HD_ / 2) + 255) / 256, 256>>>(kb, cosb, sinb, M, KV_);

    // attention (fp32)
    attn_kernel<<<dim3(S_ / AM, H_, B_), AM>>>(qb, kb, vb, amask, aob);

    // O projection (tensor cores)
    split_kernel<<<(M * NQ / 4 + 255) / 256, 256>>>(aob, aoh, aol, M * NQ / 4);
    gemm_mma<<<dim3(DM_ / 128, M / 128), 256, GSMEM>>>(aoh, aol, woh, wol, b_o, out, M, DM_, NQ);
}